// round 16
// baseline (speedup 1.0000x reference)
#include <cuda_runtime.h>
#include <cuda_fp16.h>
#include <cstdint>
#include <math.h>

#define Bn 2
#define Ln 2048
#define Dn 1024
#define Hn 16
#define DKn 64
#define BHn (Bn*Hn)      // 32
#define Mn (Bn*Ln)       // 4096

// Scratch (device globals — no allocation allowed)
__device__ __half g_q[(size_t)BHn*Ln*DKn];   // [bh][l][dk] fp16
__device__ __half g_k[(size_t)BHn*Ln*DKn];   // [bh][l][dk] fp16
__device__ __half g_vt[(size_t)BHn*DKn*Ln];  // [bh][dk][l] fp16 (transposed)
__device__ float g_o[(size_t)BHn*Ln*DKn];
__device__ unsigned long long g_mb[(size_t)Bn*Ln*(Ln/64)];  // mask bitmap
// Fallback scores buffer in case the harness output holds only `normed`
__device__ float g_sc[(size_t)BHn*Ln*Ln];

// ---- tf32 mma (projections) ----
__device__ __forceinline__ unsigned f2tf(float x) {
    unsigned r; asm("cvt.rna.tf32.f32 %0, %1;" : "=r"(r) : "f"(x));
    return r;
}
__device__ __forceinline__ void mma_tf32(float* c, const unsigned* a, const unsigned* b) {
    asm volatile(
        "mma.sync.aligned.m16n8k8.row.col.f32.tf32.tf32.f32 "
        "{%0,%1,%2,%3}, {%4,%5,%6,%7}, {%8,%9}, {%0,%1,%2,%3};"
        : "+f"(c[0]), "+f"(c[1]), "+f"(c[2]), "+f"(c[3])
        : "r"(a[0]), "r"(a[1]), "r"(a[2]), "r"(a[3]),
          "r"(b[0]), "r"(b[1]));
}

// ---- fp16 mma: D(16x8,f32) += A(16x16,f16) * B(16x8,f16) ----
__device__ __forceinline__ void mma_f16(float* c, const unsigned* a, const unsigned* b) {
    asm volatile(
        "mma.sync.aligned.m16n8k16.row.col.f32.f16.f16.f32 "
        "{%0,%1,%2,%3}, {%4,%5,%6,%7}, {%8,%9}, {%0,%1,%2,%3};"
        : "+f"(c[0]), "+f"(c[1]), "+f"(c[2]), "+f"(c[3])
        : "r"(a[0]), "r"(a[1]), "r"(a[2]), "r"(a[3]),
          "r"(b[0]), "r"(b[1]));
}

// ---- cp.async helpers ----
__device__ __forceinline__ void cp16(void* smem_dst, const void* gmem_src) {
    unsigned dst = (unsigned)__cvta_generic_to_shared(smem_dst);
    asm volatile("cp.async.cg.shared.global [%0], [%1], 16;"
                 :: "r"(dst), "l"(gmem_src));
}
__device__ __forceinline__ void cp_commit() {
    asm volatile("cp.async.commit_group;");
}
__device__ __forceinline__ unsigned h2u(__half2 h) {
    return *(unsigned*)&h;
}

// ---------------------------------------------------------------------------
// Fused projection GEMMs (z=0..2) + mask bitmap compression (z=3).
// Mask blocks are memory-bound and co-scheduled with compute-bound proj
// blocks by the SM scheduler — hides the 537 MB mask read under proj MMAs.
// ---------------------------------------------------------------------------
#define PROJ_SMEM ((2*128*36 + 2*32*136) * 4)
__global__ __launch_bounds__(256, 2) void proj_kernel(const float* __restrict__ Xk,
                                                      const float* __restrict__ Xv,
                                                      const float* __restrict__ Xq,
                                                      const float* __restrict__ Wk,
                                                      const float* __restrict__ Wv,
                                                      const float* __restrict__ Wq,
                                                      const int* __restrict__ mask) {
    const int which = blockIdx.z;
    const int tid = threadIdx.x;

    if (which == 3) {
        // ---- mask bitmap compression: 64 int32 bools -> one u64 ----
        int bid = blockIdx.y * gridDim.x + blockIdx.x;   // [0,256)
        int gw = bid * 8 + (tid >> 5);                   // [0,2048)
        int lane = tid & 31;
        #pragma unroll 4
        for (int k = 0; k < 64; k++) {
            size_t word = (size_t)gw * 64 + k;           // [0,131072)
            size_t base = word * 64;
            unsigned lo = __ballot_sync(0xffffffffu, mask[base + lane] != 0);
            unsigned hi = __ballot_sync(0xffffffffu, mask[base + 32 + lane] != 0);
            if (lane == 0)
                g_mb[word] = (unsigned long long)lo | ((unsigned long long)hi << 32);
        }
        return;
    }

    const float* X = (which == 0) ? Xk : ((which == 1) ? Xv : Xq);
    const float* W = (which == 0) ? Wk : ((which == 1) ? Wv : Wq);

    const int bm = blockIdx.y * 128;
    const int bn = blockIdx.x * 128;
    const int w = tid >> 5, lane = tid & 31;
    const int g = lane >> 2, t = lane & 3;
    const int mw = (w >> 1) * 32;
    const int nw = (w & 1) * 64;

    extern __shared__ float smem[];
    float* Xr = smem;                 // [2][128][36]
    float* Wr = smem + 2*128*36;      // [2][32][136]

    #define PROJ_STAGE(buf, k0)                                                   \
        do {                                                                      \
            float* Xd = &Xr[(size_t)(buf)*128*36];                                \
            float* Wd = &Wr[(size_t)(buf)*32*136];                                \
            _Pragma("unroll")                                                     \
            for (int it = 0; it < 4; it++) {                                      \
                int e = tid + it*256;                                             \
                int r = e >> 3, c4 = (e & 7) * 4;                                 \
                cp16(&Xd[r*36 + c4], &X[(size_t)(bm + r)*Dn + (k0) + c4]);        \
            }                                                                     \
            _Pragma("unroll")                                                     \
            for (int it = 0; it < 4; it++) {                                      \
                int e = tid + it*256;                                             \
                int kr = e >> 5, n4 = (e & 31) * 4;                               \
                cp16(&Wd[kr*136 + n4], &W[(size_t)((k0) + kr)*Dn + bn + n4]);     \
            }                                                                     \
            cp_commit();                                                          \
        } while (0)

    PROJ_STAGE(0, 0);

    float acc[2][8][4];
    #pragma unroll
    for (int mt = 0; mt < 2; mt++)
        #pragma unroll
        for (int nt = 0; nt < 8; nt++)
            #pragma unroll
            for (int c = 0; c < 4; c++) acc[mt][nt][c] = 0.f;

    const int NCH = Dn / 32;   // 32
    for (int i = 0; i < NCH; i++) {
        if (i < NCH - 1) {
            PROJ_STAGE((i + 1) & 1, (i + 1) * 32);
            asm volatile("cp.async.wait_group 1;");
        } else {
            asm volatile("cp.async.wait_group 0;");
        }
        __syncthreads();

        const float* Xc = &Xr[(size_t)(i & 1)*128*36];
        const float* Wc = &Wr[(size_t)(i & 1)*32*136];
        #pragma unroll
        for (int ks = 0; ks < 4; ks++) {
            int k = ks * 8;
            unsigned a[2][4];
            #pragma unroll
            for (int mt = 0; mt < 2; mt++) {
                int r = mw + mt*16 + g;
                a[mt][0] = f2tf(Xc[r*36 + k + t]);
                a[mt][1] = f2tf(Xc[(r+8)*36 + k + t]);
                a[mt][2] = f2tf(Xc[r*36 + k + t + 4]);
                a[mt][3] = f2tf(Xc[(r+8)*36 + k + t + 4]);
            }
            #pragma unroll
            for (int nt = 0; nt < 8; nt++) {
                int n = nw + nt*8 + g;
                unsigned b2[2];
                b2[0] = f2tf(Wc[(k+t)*136 + n]);
                b2[1] = f2tf(Wc[(k+t+4)*136 + n]);
                mma_tf32(acc[0][nt], a[0], b2);
                mma_tf32(acc[1][nt], a[1], b2);
            }
        }
        __syncthreads();
    }

    __half* outh = (which == 0) ? g_k : g_q;
    #pragma unroll
    for (int mt = 0; mt < 2; mt++) {
        #pragma unroll
        for (int h2 = 0; h2 < 2; h2++) {
            int m = bm + mw + mt*16 + h2*8 + g;
            int bb = m >> 11, l = m & (Ln-1);
            #pragma unroll
            for (int nt = 0; nt < 8; nt++) {
                int n = bn + nw + nt*8 + 2*t;
                int h = n >> 6, dk = n & 63;
                float v0 = acc[mt][nt][h2*2+0];
                float v1 = acc[mt][nt][h2*2+1];
                if (which == 1) {
                    size_t base = ((size_t)(bb*Hn + h))*DKn;
                    g_vt[(base + dk)*Ln + l]     = __float2half(v0);
                    g_vt[(base + dk + 1)*Ln + l] = __float2half(v1);
                } else {
                    *(__half2*)&outh[(((size_t)(bb*Hn + h))*Ln + l)*DKn + dk] =
                        __floats2half2_rn(v0, v1);
                }
            }
        }
    }
    #undef PROJ_STAGE
}

// ---------------------------------------------------------------------------
// Fused 2-pass attention. grid (Ln/128, BHn); 8 warps = 4m x 2n.
// Pass A: rowsums only, j-chunk 128 (K double-buffered across K+V space).
// Pass B: recompute u, p = u*ri -> attn fp32 (final), o += p*V -> g_o.
// ---------------------------------------------------------------------------
#define QH_OFF 0                    // half[128][72]   = 18432 B
#define KH_OFF 18432                // half[2][64][72] = 18432 B  (pass B)
#define VH_OFF 36864                // half[2][64][72] = 18432 B  (pass B)
// pass A reuses KH..VH as half[2][128][72]
#define MB_OFF 55296                // u64 [128][34]   = 34816 B
#define RS_OFF 90112                // float[128][2]   = 1024 B
#define FUSED_SMEM 91648
__global__ __launch_bounds__(256, 2) void fused_kernel(float* __restrict__ attn) {
    const int bh = blockIdx.y;
    const int q0 = blockIdx.x * 128;
    const int b = bh >> 4;
    const int tid = threadIdx.x;
    const int w = tid >> 5, lane = tid & 31;
    const int g = lane >> 2, t = lane & 3;
    const int mw = (w >> 1) * 32;    // q offset within tile
    const int jw = (w & 1) * 32;     // j offset within 64 subspan

    extern __shared__ char sm[];
    __half* Qh = (__half*)(sm + QH_OFF);                         // [128][72]
    __half* Kh = (__half*)(sm + KH_OFF);                         // [2][64][72]
    __half* Vh = (__half*)(sm + VH_OFF);                         // [2][64][72]
    __half* KA = (__half*)(sm + KH_OFF);                         // [2][128][72]
    unsigned long long* mb = (unsigned long long*)(sm + MB_OFF); // [128][34]
    float* rsums = (float*)(sm + RS_OFF);                        // [128][2]

    // ---- prologue staging: Q tile + mask bitmap ----
    #pragma unroll
    for (int it = 0; it < 4; it++) {
        int e = tid + it*256;                   // [0,1024)
        int r = e >> 3, c8 = (e & 7) * 8;
        cp16(&Qh[r*72 + c8], g_q + ((size_t)bh*Ln + q0 + r)*DKn + c8);
    }
    #pragma unroll
    for (int it = 0; it < 8; it++) {
        int e = tid + it*256;                   // [0,2048)
        int r = e >> 4, w2 = (e & 15) * 2;
        cp16(&mb[r*34 + w2], g_mb + ((size_t)b*Ln + q0 + r)*32 + w2);
    }
    #define STAGE_KA(buf, jc_)                                                    \
        do {                                                                      \
            __half* Kd = KA + (size_t)(buf)*128*72;                               \
            _Pragma("unroll")                                                     \
            for (int it = 0; it < 4; it++) {                                      \
                int e = tid + it*256;                                             \
                int r = e >> 3, c8 = (e & 7) * 8;                                 \
                cp16(&Kd[r*72 + c8], g_k + ((size_t)bh*Ln + (jc_) + r)*DKn + c8); \
            }                                                                     \
        } while (0)
    #define STAGE_K(buf, jc_)                                                     \
        do {                                                                      \
            __half* Kd = Kh + (size_t)(buf)*64*72;                                \
            _Pragma("unroll")                                                     \
            for (int it = 0; it < 2; it++) {                                      \
                int e = tid + it*256;                                             \
                int r = e >> 3, c8 = (e & 7) * 8;                                 \
                cp16(&Kd[r*72 + c8], g_k + ((size_t)bh*Ln + (jc_) + r)*DKn + c8); \
            }                                                                     \
        } while (0)
    #define STAGE_V(buf, jc_)                                                     \
        do {                                                                      \
            __half* Vd = Vh + (size_t)(buf)*64*72;                                \
            _Pragma("unroll")                                                     \
            for (int it = 0; it < 2; it++) {                                      \
                int e = tid + it*256;                                             \
                int r = e >> 3, c8 = (e & 7) * 8;                                 \
                cp16(&Vd[r*72 + c8], g_vt + ((size_t)bh*DKn + r)*Ln + (jc_) + c8);\
            }                                                                     \
        } while (0)

    // ================= PASS A: rowsums, j-chunk 128 =================
    STAGE_KA(0, 0);
    cp_commit();
    float rs[2][2] = {{0.f,0.f},{0.f,0.f}};

    const int NCHA = Ln / 128;   // 16
    for (int i = 0; i < NCHA; i++) {
        if (i < NCHA - 1) {
            STAGE_KA((i + 1) & 1, (i + 1) * 128);
            cp_commit();
            asm volatile("cp.async.wait_group 1;");
        } else {
            asm volatile("cp.async.wait_group 0;");
        }
        __syncthreads();
        const __half* Kc = KA + (size_t)(i & 1)*128*72;

        // mask words for this 128-chunk: words 2i and 2i+1
        unsigned long long mwd[2][2][2];
        #pragma unroll
        for (int mt = 0; mt < 2; mt++)
            #pragma unroll
            for (int h2 = 0; h2 < 2; h2++) {
                mwd[mt][h2][0] = mb[(mw + mt*16 + h2*8 + g)*34 + 2*i];
                mwd[mt][h2][1] = mb[(mw + mt*16 + h2*8 + g)*34 + 2*i + 1];
            }

        #pragma unroll
        for (int sub = 0; sub < 4; sub++) {
            const int half64 = sub >> 1;               // which 64-span
            const int jb = half64*64 + jw + (sub & 1)*16;
            float sacc[2][2][4];
            #pragma unroll
            for (int mt = 0; mt < 2; mt++)
                #pragma unroll
                for (int n2 = 0; n2 < 2; n2++)
                    #pragma unroll
                    for (int c = 0; c < 4; c++) sacc[mt][n2][c] = 0.f;
            #pragma unroll
            for (int ks = 0; ks < 4; ks++) {
                int k2 = ks * 16;
                unsigned a[2][4];
                #pragma unroll
                for (int mt = 0; mt < 2; mt++) {
                    int r = mw + mt*16 + g;
                    a[mt][0] = *(const unsigned*)&Qh[r*72 + k2 + 2*t];
                    a[mt][1] = *(const unsigned*)&Qh[(r+8)*72 + k2 + 2*t];
                    a[mt][2] = *(const unsigned*)&Qh[r*72 + k2 + 2*t + 8];
                    a[mt][3] = *(const unsigned*)&Qh[(r+8)*72 + k2 + 2*t + 8];
                }
                #pragma unroll
                for (int n2 = 0; n2 < 2; n2++) {
                    int rj = jb + n2*8 + g;
                    unsigned bb[2];
                    bb[0] = *(const unsigned*)&Kc[rj*72 + k2 + 2*t];
                    bb[1] = *(const unsigned*)&Kc[rj*72 + k2 + 2*t + 8];
                    mma_f16(sacc[0][n2], a[0], bb);
                    mma_f16(sacc[1][n2], a[1], bb);
                }
            }
            #pragma unroll
            for (int mt = 0; mt < 2; mt++) {
                #pragma unroll
                for (int n2 = 0; n2 < 2; n2++) {
                    int boff = jw + (sub & 1)*16 + n2*8 + 2*t;
                    unsigned long long m0 = mwd[mt][0][half64] >> boff;
                    unsigned long long m1 = mwd[mt][1][half64] >> boff;
                    rs[mt][0] += ((m0 & 1ull) ? 0.f : __expf(sacc[mt][n2][0]*0.125f))
                               + ((m0 & 2ull) ? 0.f : __expf(sacc[mt][n2][1]*0.125f));
                    rs[mt][1] += ((m1 & 1ull) ? 0.f : __expf(sacc[mt][n2][2]*0.125f))
                               + ((m1 & 2ull) ? 0.f : __expf(sacc[mt][n2][3]*0.125f));
                }
            }
        }
        __syncthreads();
    }

    // rowsum reduce (t-lanes, then both n-warps via smem) -> ri in rsums[q][0]
    #pragma unroll
    for (int mt = 0; mt < 2; mt++)
        #pragma unroll
        for (int h2 = 0; h2 < 2; h2++) {
            float v = rs[mt][h2];
            v += __shfl_xor_sync(0xffffffffu, v, 1);
            v += __shfl_xor_sync(0xffffffffu, v, 2);
            if (t == 0)
                rsums[(mw + mt*16 + h2*8 + g)*2 + (w & 1)] = v;
        }
    __syncthreads();
    if (tid < 128)
        rsums[tid*2] = 1.0f / (rsums[tid*2] + rsums[tid*2 + 1]);
    __syncthreads();

    float rith[2][2];
    #pragma unroll
    for (int mt = 0; mt < 2; mt++) {
        rith[mt][0] = rsums[(mw + mt*16 + g)*2];
        rith[mt][1] = rsums[(mw + mt*16 + 8 + g)*2];
    }

    // ================= PASS B: attn write + PV (j-chunk 64) =================
    STAGE_K(0, 0);
    STAGE_V(0, 0);
    cp_commit();

    float oacc[2][8][4];
    #pragma unroll
    for (int mt = 0; mt < 2; mt++)
        #pragma unroll
        for (int nt = 0; nt < 8; nt++)
            #pragma unroll
            for (int c = 0; c < 4; c++) oacc[mt][nt][c] = 0.f;

    const int NCH = Ln / 64;   // 32
    for (int i = 0; i < NCH; i++) {
        const int jc = i * 64;
        if (i < NCH - 1) {
            STAGE_K((i + 1) & 1, jc + 64);
            STAGE_V((i + 1) & 1, jc + 64);
            cp_commit();
            asm volatile("cp.async.wait_group 1;");
        } else {
            asm volatile("cp.async.wait_group 0;");
        }
        __syncthreads();

        const __half* Kc = Kh + (size_t)(i & 1)*64*72;
        const __half* Vc = Vh + (size_t)(i & 1)*64*72;

        unsigned long long mwd[2][2];
        #pragma unroll
        for (int mt = 0; mt < 2; mt++)
            #pragma unroll
            for (int h2 = 0; h2 < 2; h2++)
                mwd[mt][h2] = mb[(mw + mt*16 + h2*8 + g)*34 + i];

        #pragma unroll
        for (int sub = 0; sub < 2; sub++) {
            const int jb = jw + sub*16;
            float sacc[2][2][4];
            #pragma unroll
            for (int mt = 0; mt < 2; mt++)
                #pragma unroll
                for (int n2 = 0; n2 < 2; n2++)
                    #pragma unroll
                    for (int c = 0; c < 4; c++) sacc[mt][n2][c] = 0.f;
            #pragma unroll
            for (int ks = 0; ks < 4; ks++) {
                int k2 = ks * 16;
                unsigned a[2][4];
                #pragma unroll
                for (int mt = 0; mt < 2; mt++) {
                    int r = mw + mt*16 + g;
                    a[mt][0] = *(const unsigned*)&Qh[r*72 + k2 + 2*t];
                    a[mt][1] = *(const unsigned*)&Qh[(r+8)*72 + k2 + 2*t];
                    a[mt][2] = *(const unsigned*)&Qh[r*72 + k2 + 2*t + 8];
                    a[mt][3] = *(const unsigned*)&Qh[(r+8)*72 + k2 + 2*t + 8];
                }
                #pragma unroll
                for (int n2 = 0; n2 < 2; n2++) {
                    int rj = jb + n2*8 + g;
                    unsigned bb[2];
                    bb[0] = *(const unsigned*)&Kc[rj*72 + k2 + 2*t];
                    bb[1] = *(const unsigned*)&Kc[rj*72 + k2 + 2*t + 8];
                    mma_f16(sacc[0][n2], a[0], bb);
                    mma_f16(sacc[1][n2], a[1], bb);
                }
            }
            // epilogue: exp, normalize, write attn fp32, build p frags
            unsigned pa[2][4];
            #pragma unroll
            for (int mt = 0; mt < 2; mt++) {
                float pp[2][4];
                #pragma unroll
                for (int n2 = 0; n2 < 2; n2++) {
                    int boff = jb + n2*8 + 2*t;
                    unsigned long long m0 = mwd[mt][0] >> boff;
                    unsigned long long m1 = mwd[mt][1] >> boff;
                    pp[n2][0] = (m0 & 1ull) ? 0.f
                              : __expf(sacc[mt][n2][0]*0.125f) * rith[mt][0];
                    pp[n2][1] = (m0 & 2ull) ? 0.f
                              : __expf(sacc[mt][n2][1]*0.125f) * rith[mt][0];
                    pp[n2][2] = (m1 & 1ull) ? 0.f
                              : __expf(sacc[mt][n2][2]*0.125f) * rith[mt][1];
                    pp[n2][3] = (m1 & 2ull) ? 0.f
                              : __expf(sacc[mt][n2][3]*0.125f) * rith[mt][1];
                    int qrow = q0 + mw + mt*16 + g;
                    size_t base = ((size_t)bh*Ln + qrow)*Ln + jc + boff;
                    *(float2*)(attn + base) = make_float2(pp[n2][0], pp[n2][1]);
                    *(float2*)(attn + base + (size_t)8*Ln) =
                        make_float2(pp[n2][2], pp[n2][3]);
                }
                pa[mt][0] = h2u(__floats2half2_rn(pp[0][0], pp[0][1]));
                pa[mt][1] = h2u(__floats2half2_rn(pp[0][2], pp[0][3]));
                pa[mt][2] = h2u(__floats2half2_rn(pp[1][0], pp[1][1]));
                pa[mt][3] = h2u(__floats2half2_rn(pp[1][2], pp[1][3]));
            }
            // PV: o += p(16j) * V
            #pragma unroll
            for (int ntd = 0; ntd < 8; ntd++) {
                int n = ntd*8 + g;
                unsigned bv[2];
                bv[0] = *(const unsigned*)&Vc[n*72 + jb + 2*t];
                bv[1] = *(const unsigned*)&Vc[n*72 + jb + 2*t + 8];
                mma_f16(oacc[0][ntd], pa[0], bv);
                mma_f16(oacc[1][ntd], pa[1], bv);
            }
        }
        __syncthreads();
    }

    // ---- cross-warp O reduction (odd warps stash, even warps finalize) ----
    float* Osm = (float*)(sm + KH_OFF);    // [128][66] floats (reuses K/V space)
    if (w & 1) {
        #pragma unroll
        for (int mt = 0; mt < 2; mt++) {
            int ql = mw + mt*16 + g;
            #pragma unroll
            for (int ntd = 0; ntd < 8; ntd++) {
                int dk = ntd*8 + 2*t;
                *(float2*)&Osm[ql*66 + dk] =
                    make_float2(oacc[mt][ntd][0], oacc[mt][ntd][1]);
                *(float2*)&Osm[(ql+8)*66 + dk] =
                    make_float2(oacc[mt][ntd][2], oacc[mt][ntd][3]);
            }
        }
    }
    __syncthreads();
    if (!(w & 1)) {
        #pragma unroll
        for (int mt = 0; mt < 2; mt++) {
            int ql = mw + mt*16 + g;
            #pragma unroll
            for (int ntd = 0; ntd < 8; ntd++) {
                int dk = ntd*8 + 2*t;
                float2 s0 = *(float2*)&Osm[ql*66 + dk];
                float2 s8 = *(float2*)&Osm[(ql+8)*66 + dk];
                size_t ob = ((size_t)bh*Ln + q0 + ql)*DKn + dk;
                *(float2*)&g_o[ob] =
                    make_float2(oacc[mt][ntd][0]+s0.x, oacc[mt][ntd][1]+s0.y);
                *(float2*)&g_o[ob + (size_t)8*DKn] =
                    make_float2(oacc[mt][ntd][2]+s8.x, oacc[mt][ntd][3]+s8.y);
            }
        }
    }
    #undef STAGE_KA
    #undef STAGE_K
    #undef STAGE_V
}

// ---------------------------------------------------------------------------
// Residual + LayerNorm (unchanged)
// ---------------------------------------------------------------------------
__global__ __launch_bounds__(256) void ln_kernel(const float* __restrict__ query,
                                                 const float* __restrict__ gamma,
                                                 const float* __restrict__ beta,
                                                 float* __restrict__ out) {
    const int row = blockIdx.x;
    const int b = row >> 11, l = row & (Ln-1);
    const int tid = threadIdx.x;
    float vals[4];
    float s = 0.f, ss = 0.f;
    #pragma unroll
    for (int it = 0; it < 4; it++) {
        int d = tid + it*256;
        int h = d >> 6, dk = d & 63;
        float o = g_o[(((size_t)(b*Hn + h))*Ln + l)*DKn + dk];
        float r = o + query[(size_t)row*Dn + d];
        vals[it] = r;
        s += r; ss += r*r;
    }
    __shared__ float sm[8], sq[8], stat[2];
    #pragma unroll
    for (int off = 16; off; off >>= 1) {
        s  += __shfl_xor_sync(0xffffffffu, s, off);
        ss += __shfl_xor_sync(0xffffffffu, ss, off);
    }
    int warp = tid >> 5, lane = tid & 31;
    if (lane == 0) { sm[warp] = s; sq[warp] = ss; }
    __syncthreads();
    if (tid == 0) {
        float S = 0.f, SS = 0.f;
        #pragma unroll
        for (int w = 0; w < 8; w++) { S += sm[w]; SS += sq[w]; }
        float mu = S * (1.0f/Dn);
        float var = SS * (1.0f/Dn) - mu*mu;
        stat[0] = mu;
        stat[1] = rsqrtf(var + 1e-6f);
    }
    __syncthreads();
    float mu = stat[0], rstd = stat[1];
    #pragma unroll
    for (int it = 0; it < 4; it++) {
        int d = tid + it*256;
        out[(size_t)row*Dn + d] = (vals[it] - mu) * rstd * gamma[d] + beta[d];
    }
}

// ---------------------------------------------------------------------------
extern "C" void kernel_launch(void* const* d_in, const int* in_sizes, int n_in,
                              void* d_out, int out_size) {
    const float* key   = (const float*)d_in[0];
    const float* value = (const float*)d_in[1];
    const float* query = (const float*)d_in[2];
    const int*   mask  = (const int*)d_in[3];
    const float* Wk = (const float*)d_in[4];
    const float* Wv = (const float*)d_in[5];
    const float* Wq = (const float*)d_in[6];
    const float* lng = (const float*)d_in[7];
    const float* lnb = (const float*)d_in[8];

    float* normed = (float*)d_out;                       // [B, L, D]
    float* attn;
    if ((size_t)out_size > (size_t)Bn*Ln*Dn) {
        attn = normed + (size_t)Bn*Ln*Dn;                // [B*H, L, L]
    } else {
        cudaGetSymbolAddress((void**)&attn, g_sc);
    }

    cudaFuncSetAttribute(proj_kernel,
                         cudaFuncAttributeMaxDynamicSharedMemorySize, PROJ_SMEM);
    cudaFuncSetAttribute(fused_kernel,
                         cudaFuncAttributeMaxDynamicSharedMemorySize, FUSED_SMEM);

    dim3 gp(Dn/128, Mn/128, 4);   // z=0..2 proj K/V/Q, z=3 mask compression
    proj_kernel<<<gp, 256, PROJ_SMEM>>>(key, value, query, Wk, Wv, Wq, mask);

    dim3 gf(Ln/128, BHn);         // (16, 32)
    fused_kernel<<<gf, 256, FUSED_SMEM>>>(attn);

    ln_kernel<<<Mn, 256>>>(query, lng, lnb, normed);
}

// round 17
// speedup vs baseline: 1.0191x; 1.0191x over previous
#include <cuda_runtime.h>
#include <cuda_fp16.h>
#include <cstdint>
#include <math.h>

#define Bn 2
#define Ln 2048
#define Dn 1024
#define Hn 16
#define DKn 64
#define BHn (Bn*Hn)      // 32
#define Mn (Bn*Ln)       // 4096

// Scratch (device globals — no allocation allowed)
__device__ __half g_q[(size_t)BHn*Ln*DKn];   // [bh][l][dk] fp16
__device__ __half g_k[(size_t)BHn*Ln*DKn];   // [bh][l][dk] fp16
__device__ __half g_vt[(size_t)BHn*DKn*Ln];  // [bh][dk][l] fp16 (transposed)
__device__ float g_o[(size_t)BHn*Ln*DKn];
__device__ unsigned long long g_mb[(size_t)Bn*Ln*(Ln/64)];  // mask bitmap
// Fallback scores buffer in case the harness output holds only `normed`
__device__ float g_sc[(size_t)BHn*Ln*Ln];

// ---- tf32 mma (projections) ----
__device__ __forceinline__ unsigned f2tf(float x) {
    unsigned r; asm("cvt.rna.tf32.f32 %0, %1;" : "=r"(r) : "f"(x));
    return r;
}
__device__ __forceinline__ void mma_tf32(float* c, const unsigned* a, const unsigned* b) {
    asm volatile(
        "mma.sync.aligned.m16n8k8.row.col.f32.tf32.tf32.f32 "
        "{%0,%1,%2,%3}, {%4,%5,%6,%7}, {%8,%9}, {%0,%1,%2,%3};"
        : "+f"(c[0]), "+f"(c[1]), "+f"(c[2]), "+f"(c[3])
        : "r"(a[0]), "r"(a[1]), "r"(a[2]), "r"(a[3]),
          "r"(b[0]), "r"(b[1]));
}

// ---- fp16 mma: D(16x8,f32) += A(16x16,f16) * B(16x8,f16) ----
__device__ __forceinline__ void mma_f16(float* c, const unsigned* a, const unsigned* b) {
    asm volatile(
        "mma.sync.aligned.m16n8k16.row.col.f32.f16.f16.f32 "
        "{%0,%1,%2,%3}, {%4,%5,%6,%7}, {%8,%9}, {%0,%1,%2,%3};"
        : "+f"(c[0]), "+f"(c[1]), "+f"(c[2]), "+f"(c[3])
        : "r"(a[0]), "r"(a[1]), "r"(a[2]), "r"(a[3]),
          "r"(b[0]), "r"(b[1]));
}

// ---- cp.async helpers ----
__device__ __forceinline__ void cp16(void* smem_dst, const void* gmem_src) {
    unsigned dst = (unsigned)__cvta_generic_to_shared(smem_dst);
    asm volatile("cp.async.cg.shared.global [%0], [%1], 16;"
                 :: "r"(dst), "l"(gmem_src));
}
__device__ __forceinline__ void cp_commit() {
    asm volatile("cp.async.commit_group;");
}
__device__ __forceinline__ unsigned h2u(__half2 h) {
    return *(unsigned*)&h;
}

// ---------------------------------------------------------------------------
// Fused projection GEMMs (x=0..2) + mask bitmap compression (x=3).
// Selector on blockIdx.x (fastest-varying): consecutive linear block IDs
// cycle K/V/Q/mask, so mask (memory-bound) co-runs with proj (tensor-bound)
// in every wave, hiding the 537 MB mask read.
// grid (4, Dn/128=8, Mn/128=32).
// ---------------------------------------------------------------------------
#define PROJ_SMEM ((2*128*36 + 2*32*136) * 4)
__global__ __launch_bounds__(256, 2) void proj_kernel(const float* __restrict__ Xk,
                                                      const float* __restrict__ Xv,
                                                      const float* __restrict__ Xq,
                                                      const float* __restrict__ Wk,
                                                      const float* __restrict__ Wv,
                                                      const float* __restrict__ Wq,
                                                      const int* __restrict__ mask) {
    const int which = blockIdx.x;
    const int tid = threadIdx.x;

    if (which == 3) {
        // ---- mask bitmap compression: 64 int32 bools -> one u64 ----
        int bid = blockIdx.z * gridDim.y + blockIdx.y;   // [0,256)
        int gw = bid * 8 + (tid >> 5);                   // [0,2048)
        int lane = tid & 31;
        #pragma unroll 4
        for (int k = 0; k < 64; k++) {
            size_t word = (size_t)gw * 64 + k;           // [0,131072)
            size_t base = word * 64;
            unsigned lo = __ballot_sync(0xffffffffu, mask[base + lane] != 0);
            unsigned hi = __ballot_sync(0xffffffffu, mask[base + 32 + lane] != 0);
            if (lane == 0)
                g_mb[word] = (unsigned long long)lo | ((unsigned long long)hi << 32);
        }
        return;
    }

    const float* X = (which == 0) ? Xk : ((which == 1) ? Xv : Xq);
    const float* W = (which == 0) ? Wk : ((which == 1) ? Wv : Wq);

    const int bm = blockIdx.z * 128;
    const int bn = blockIdx.y * 128;
    const int w = tid >> 5, lane = tid & 31;
    const int g = lane >> 2, t = lane & 3;
    const int mw = (w >> 1) * 32;
    const int nw = (w & 1) * 64;

    extern __shared__ float smem[];
    float* Xr = smem;                 // [2][128][36]
    float* Wr = smem + 2*128*36;      // [2][32][136]

    #define PROJ_STAGE(buf, k0)                                                   \
        do {                                                                      \
            float* Xd = &Xr[(size_t)(buf)*128*36];                                \
            float* Wd = &Wr[(size_t)(buf)*32*136];                                \
            _Pragma("unroll")                                                     \
            for (int it = 0; it < 4; it++) {                                      \
                int e = tid + it*256;                                             \
                int r = e >> 3, c4 = (e & 7) * 4;                                 \
                cp16(&Xd[r*36 + c4], &X[(size_t)(bm + r)*Dn + (k0) + c4]);        \
            }                                                                     \
            _Pragma("unroll")                                                     \
            for (int it = 0; it < 4; it++) {                                      \
                int e = tid + it*256;                                             \
                int kr = e >> 5, n4 = (e & 31) * 4;                               \
                cp16(&Wd[kr*136 + n4], &W[(size_t)((k0) + kr)*Dn + bn + n4]);     \
            }                                                                     \
            cp_commit();                                                          \
        } while (0)

    PROJ_STAGE(0, 0);

    float acc[2][8][4];
    #pragma unroll
    for (int mt = 0; mt < 2; mt++)
        #pragma unroll
        for (int nt = 0; nt < 8; nt++)
            #pragma unroll
            for (int c = 0; c < 4; c++) acc[mt][nt][c] = 0.f;

    const int NCH = Dn / 32;   // 32
    for (int i = 0; i < NCH; i++) {
        if (i < NCH - 1) {
            PROJ_STAGE((i + 1) & 1, (i + 1) * 32);
            asm volatile("cp.async.wait_group 1;");
        } else {
            asm volatile("cp.async.wait_group 0;");
        }
        __syncthreads();

        const float* Xc = &Xr[(size_t)(i & 1)*128*36];
        const float* Wc = &Wr[(size_t)(i & 1)*32*136];
        #pragma unroll
        for (int ks = 0; ks < 4; ks++) {
            int k = ks * 8;
            unsigned a[2][4];
            #pragma unroll
            for (int mt = 0; mt < 2; mt++) {
                int r = mw + mt*16 + g;
                a[mt][0] = f2tf(Xc[r*36 + k + t]);
                a[mt][1] = f2tf(Xc[(r+8)*36 + k + t]);
                a[mt][2] = f2tf(Xc[r*36 + k + t + 4]);
                a[mt][3] = f2tf(Xc[(r+8)*36 + k + t + 4]);
            }
            #pragma unroll
            for (int nt = 0; nt < 8; nt++) {
                int n = nw + nt*8 + g;
                unsigned b2[2];
                b2[0] = f2tf(Wc[(k+t)*136 + n]);
                b2[1] = f2tf(Wc[(k+t+4)*136 + n]);
                mma_tf32(acc[0][nt], a[0], b2);
                mma_tf32(acc[1][nt], a[1], b2);
            }
        }
        __syncthreads();
    }

    __half* outh = (which == 0) ? g_k : g_q;
    #pragma unroll
    for (int mt = 0; mt < 2; mt++) {
        #pragma unroll
        for (int h2 = 0; h2 < 2; h2++) {
            int m = bm + mw + mt*16 + h2*8 + g;
            int bb = m >> 11, l = m & (Ln-1);
            #pragma unroll
            for (int nt = 0; nt < 8; nt++) {
                int n = bn + nw + nt*8 + 2*t;
                int h = n >> 6, dk = n & 63;
                float v0 = acc[mt][nt][h2*2+0];
                float v1 = acc[mt][nt][h2*2+1];
                if (which == 1) {
                    size_t base = ((size_t)(bb*Hn + h))*DKn;
                    g_vt[(base + dk)*Ln + l]     = __float2half(v0);
                    g_vt[(base + dk + 1)*Ln + l] = __float2half(v1);
                } else {
                    *(__half2*)&outh[(((size_t)(bb*Hn + h))*Ln + l)*DKn + dk] =
                        __floats2half2_rn(v0, v1);
                }
            }
        }
    }
    #undef PROJ_STAGE
}

// ---------------------------------------------------------------------------
// Fused 2-pass attention (round-15 validated structure, 64-j chunks).
// grid (Ln/128, BHn); 8 warps = 4m x 2n.
// Pass A: rowsums (QK^T + mask + exp, no stores).
// Pass B: recompute u, p = u*ri -> attn fp32 (final), o += p*V -> g_o.
// ---------------------------------------------------------------------------
#define QH_OFF 0                    // half[128][72]   = 18432 B
#define KH_OFF 18432                // half[2][64][72] = 18432 B
#define VH_OFF 36864                // half[2][64][72] = 18432 B
#define MB_OFF 55296                // u64 [128][34]   = 34816 B
#define RS_OFF 90112                // float[128][2]   = 1024 B
#define FUSED_SMEM 91648
__global__ __launch_bounds__(256, 2) void fused_kernel(float* __restrict__ attn) {
    const int bh = blockIdx.y;
    const int q0 = blockIdx.x * 128;
    const int b = bh >> 4;
    const int tid = threadIdx.x;
    const int w = tid >> 5, lane = tid & 31;
    const int g = lane >> 2, t = lane & 3;
    const int mw = (w >> 1) * 32;    // q offset within tile
    const int jw = (w & 1) * 32;     // j offset within 64-chunk

    extern __shared__ char sm[];
    __half* Qh = (__half*)(sm + QH_OFF);                         // [128][72]
    __half* Kh = (__half*)(sm + KH_OFF);                         // [2][64][72]
    __half* Vh = (__half*)(sm + VH_OFF);                         // [2][64][72]
    unsigned long long* mb = (unsigned long long*)(sm + MB_OFF); // [128][34]
    float* rsums = (float*)(sm + RS_OFF);                        // [128][2]

    // ---- prologue staging: Q tile + mask bitmap ----
    #pragma unroll
    for (int it = 0; it < 4; it++) {
        int e = tid + it*256;                   // [0,1024)
        int r = e >> 3, c8 = (e & 7) * 8;
        cp16(&Qh[r*72 + c8], g_q + ((size_t)bh*Ln + q0 + r)*DKn + c8);
    }
    #pragma unroll
    for (int it = 0; it < 8; it++) {
        int e = tid + it*256;                   // [0,2048)
        int r = e >> 4, w2 = (e & 15) * 2;
        cp16(&mb[r*34 + w2], g_mb + ((size_t)b*Ln + q0 + r)*32 + w2);
    }
    #define STAGE_K(buf, jc_)                                                     \
        do {                                                                      \
            __half* Kd = Kh + (size_t)(buf)*64*72;                                \
            _Pragma("unroll")                                                     \
            for (int it = 0; it < 2; it++) {                                      \
                int e = tid + it*256;                                             \
                int r = e >> 3, c8 = (e & 7) * 8;                                 \
                cp16(&Kd[r*72 + c8], g_k + ((size_t)bh*Ln + (jc_) + r)*DKn + c8); \
            }                                                                     \
        } while (0)
    #define STAGE_V(buf, jc_)                                                     \
        do {                                                                      \
            __half* Vd = Vh + (size_t)(buf)*64*72;                                \
            _Pragma("unroll")                                                     \
            for (int it = 0; it < 2; it++) {                                      \
                int e = tid + it*256;                                             \
                int r = e >> 3, c8 = (e & 7) * 8;                                 \
                cp16(&Vd[r*72 + c8], g_vt + ((size_t)bh*DKn + r)*Ln + (jc_) + c8);\
            }                                                                     \
        } while (0)

    const int NCH = Ln / 64;   // 32

    // ================= PASS A: rowsums =================
    STAGE_K(0, 0);
    cp_commit();
    float rs[2][2] = {{0.f,0.f},{0.f,0.f}};

    for (int i = 0; i < NCH; i++) {
        if (i < NCH - 1) {
            STAGE_K((i + 1) & 1, (i + 1) * 64);
            cp_commit();
            asm volatile("cp.async.wait_group 1;");
        } else {
            asm volatile("cp.async.wait_group 0;");
        }
        __syncthreads();
        const __half* Kc = Kh + (size_t)(i & 1)*64*72;

        unsigned long long mwd[2][2];
        #pragma unroll
        for (int mt = 0; mt < 2; mt++)
            #pragma unroll
            for (int h2 = 0; h2 < 2; h2++)
                mwd[mt][h2] = mb[(mw + mt*16 + h2*8 + g)*34 + i];

        #pragma unroll
        for (int sub = 0; sub < 2; sub++) {
            const int jb = jw + sub*16;
            float sacc[2][2][4];
            #pragma unroll
            for (int mt = 0; mt < 2; mt++)
                #pragma unroll
                for (int n2 = 0; n2 < 2; n2++)
                    #pragma unroll
                    for (int c = 0; c < 4; c++) sacc[mt][n2][c] = 0.f;
            #pragma unroll
            for (int ks = 0; ks < 4; ks++) {
                int k2 = ks * 16;
                unsigned a[2][4];
                #pragma unroll
                for (int mt = 0; mt < 2; mt++) {
                    int r = mw + mt*16 + g;
                    a[mt][0] = *(const unsigned*)&Qh[r*72 + k2 + 2*t];
                    a[mt][1] = *(const unsigned*)&Qh[(r+8)*72 + k2 + 2*t];
                    a[mt][2] = *(const unsigned*)&Qh[r*72 + k2 + 2*t + 8];
                    a[mt][3] = *(const unsigned*)&Qh[(r+8)*72 + k2 + 2*t + 8];
                }
                #pragma unroll
                for (int n2 = 0; n2 < 2; n2++) {
                    int rj = jb + n2*8 + g;
                    unsigned bb[2];
                    bb[0] = *(const unsigned*)&Kc[rj*72 + k2 + 2*t];
                    bb[1] = *(const unsigned*)&Kc[rj*72 + k2 + 2*t + 8];
                    mma_f16(sacc[0][n2], a[0], bb);
                    mma_f16(sacc[1][n2], a[1], bb);
                }
            }
            #pragma unroll
            for (int mt = 0; mt < 2; mt++) {
                #pragma unroll
                for (int n2 = 0; n2 < 2; n2++) {
                    int boff = jb + n2*8 + 2*t;
                    unsigned long long m0 = mwd[mt][0] >> boff;
                    unsigned long long m1 = mwd[mt][1] >> boff;
                    rs[mt][0] += ((m0 & 1ull) ? 0.f : __expf(sacc[mt][n2][0]*0.125f))
                               + ((m0 & 2ull) ? 0.f : __expf(sacc[mt][n2][1]*0.125f));
                    rs[mt][1] += ((m1 & 1ull) ? 0.f : __expf(sacc[mt][n2][2]*0.125f))
                               + ((m1 & 2ull) ? 0.f : __expf(sacc[mt][n2][3]*0.125f));
                }
            }
        }
        __syncthreads();
    }

    // rowsum reduce (t-lanes, then both n-warps via smem) -> ri in rsums[q][0]
    #pragma unroll
    for (int mt = 0; mt < 2; mt++)
        #pragma unroll
        for (int h2 = 0; h2 < 2; h2++) {
            float v = rs[mt][h2];
            v += __shfl_xor_sync(0xffffffffu, v, 1);
            v += __shfl_xor_sync(0xffffffffu, v, 2);
            if (t == 0)
                rsums[(mw + mt*16 + h2*8 + g)*2 + (w & 1)] = v;
        }
    __syncthreads();
    if (tid < 128)
        rsums[tid*2] = 1.0f / (rsums[tid*2] + rsums[tid*2 + 1]);
    __syncthreads();

    float rith[2][2];
    #pragma unroll
    for (int mt = 0; mt < 2; mt++) {
        rith[mt][0] = rsums[(mw + mt*16 + g)*2];
        rith[mt][1] = rsums[(mw + mt*16 + 8 + g)*2];
    }

    // ================= PASS B: attn write + PV =================
    STAGE_K(0, 0);
    STAGE_V(0, 0);
    cp_commit();

    float oacc[2][8][4];
    #pragma unroll
    for (int mt = 0; mt < 2; mt++)
        #pragma unroll
        for (int nt = 0; nt < 8; nt++)
            #pragma unroll
            for (int c = 0; c < 4; c++) oacc[mt][nt][c] = 0.f;

    for (int i = 0; i < NCH; i++) {
        const int jc = i * 64;
        if (i < NCH - 1) {
            STAGE_K((i + 1) & 1, jc + 64);
            STAGE_V((i + 1) & 1, jc + 64);
            cp_commit();
            asm volatile("cp.async.wait_group 1;");
        } else {
            asm volatile("cp.async.wait_group 0;");
        }
        __syncthreads();

        const __half* Kc = Kh + (size_t)(i & 1)*64*72;
        const __half* Vc = Vh + (size_t)(i & 1)*64*72;

        unsigned long long mwd[2][2];
        #pragma unroll
        for (int mt = 0; mt < 2; mt++)
            #pragma unroll
            for (int h2 = 0; h2 < 2; h2++)
                mwd[mt][h2] = mb[(mw + mt*16 + h2*8 + g)*34 + i];

        #pragma unroll
        for (int sub = 0; sub < 2; sub++) {
            const int jb = jw + sub*16;
            float sacc[2][2][4];
            #pragma unroll
            for (int mt = 0; mt < 2; mt++)
                #pragma unroll
                for (int n2 = 0; n2 < 2; n2++)
                    #pragma unroll
                    for (int c = 0; c < 4; c++) sacc[mt][n2][c] = 0.f;
            #pragma unroll
            for (int ks = 0; ks < 4; ks++) {
                int k2 = ks * 16;
                unsigned a[2][4];
                #pragma unroll
                for (int mt = 0; mt < 2; mt++) {
                    int r = mw + mt*16 + g;
                    a[mt][0] = *(const unsigned*)&Qh[r*72 + k2 + 2*t];
                    a[mt][1] = *(const unsigned*)&Qh[(r+8)*72 + k2 + 2*t];
                    a[mt][2] = *(const unsigned*)&Qh[r*72 + k2 + 2*t + 8];
                    a[mt][3] = *(const unsigned*)&Qh[(r+8)*72 + k2 + 2*t + 8];
                }
                #pragma unroll
                for (int n2 = 0; n2 < 2; n2++) {
                    int rj = jb + n2*8 + g;
                    unsigned bb[2];
                    bb[0] = *(const unsigned*)&Kc[rj*72 + k2 + 2*t];
                    bb[1] = *(const unsigned*)&Kc[rj*72 + k2 + 2*t + 8];
                    mma_f16(sacc[0][n2], a[0], bb);
                    mma_f16(sacc[1][n2], a[1], bb);
                }
            }
            // epilogue: exp, normalize, write attn fp32, build p frags
            unsigned pa[2][4];
            #pragma unroll
            for (int mt = 0; mt < 2; mt++) {
                float pp[2][4];
                #pragma unroll
                for (int n2 = 0; n2 < 2; n2++) {
                    int boff = jb + n2*8 + 2*t;
                    unsigned long long m0 = mwd[mt][0] >> boff;
                    unsigned long long m1 = mwd[mt][1] >> boff;
                    pp[n2][0] = (m0 & 1ull) ? 0.f
                              : __expf(sacc[mt][n2][0]*0.125f) * rith[mt][0];
                    pp[n2][1] = (m0 & 2ull) ? 0.f
                              : __expf(sacc[mt][n2][1]*0.125f) * rith[mt][0];
                    pp[n2][2] = (m1 & 1ull) ? 0.f
                              : __expf(sacc[mt][n2][2]*0.125f) * rith[mt][1];
                    pp[n2][3] = (m1 & 2ull) ? 0.f
                              : __expf(sacc[mt][n2][3]*0.125f) * rith[mt][1];
                    int qrow = q0 + mw + mt*16 + g;
                    size_t base = ((size_t)bh*Ln + qrow)*Ln + jc + boff;
                    *(float2*)(attn + base) = make_float2(pp[n2][0], pp[n2][1]);
                    *(float2*)(attn + base + (size_t)8*Ln) =
                        make_float2(pp[n2][2], pp[n2][3]);
                }
                pa[mt][0] = h2u(__floats2half2_rn(pp[0][0], pp[0][1]));
                pa[mt][1] = h2u(__floats2half2_rn(pp[0][2], pp[0][3]));
                pa[mt][2] = h2u(__floats2half2_rn(pp[1][0], pp[1][1]));
                pa[mt][3] = h2u(__floats2half2_rn(pp[1][2], pp[1][3]));
            }
            // PV: o += p(16j) * V
            #pragma unroll
            for (int ntd = 0; ntd < 8; ntd++) {
                int n = ntd*8 + g;
                unsigned bv[2];
                bv[0] = *(const unsigned*)&Vc[n*72 + jb + 2*t];
                bv[1] = *(const unsigned*)&Vc[n*72 + jb + 2*t + 8];
                mma_f16(oacc[0][ntd], pa[0], bv);
                mma_f16(oacc[1][ntd], pa[1], bv);
            }
        }
        __syncthreads();
    }

    // ---- cross-warp O reduction (odd warps stash, even warps finalize) ----
    float* Osm = (float*)(sm + KH_OFF);    // [128][66] floats (reuses K/V space)
    if (w & 1) {
        #pragma unroll
        for (int mt = 0; mt < 2; mt++) {
            int ql = mw + mt*16 + g;
            #pragma unroll
            for (int ntd = 0; ntd < 8; ntd++) {
                int dk = ntd*8 + 2*t;
                *(float2*)&Osm[ql*66 + dk] =
                    make_float2(oacc[mt][ntd][0], oacc[mt][ntd][1]);
                *(float2*)&Osm[(ql+8)*66 + dk] =
                    make_float2(oacc[mt][ntd][2], oacc[mt][ntd][3]);
            }
        }
    }
    __syncthreads();
    if (!(w & 1)) {
        #pragma unroll
        for (int mt = 0; mt < 2; mt++) {
            int ql = mw + mt*16 + g;
            #pragma unroll
            for (int ntd = 0; ntd < 8; ntd++) {
                int dk = ntd*8 + 2*t;
                float2 s0 = *(float2*)&Osm[ql*66 + dk];
                float2 s8 = *(float2*)&Osm[(ql+8)*66 + dk];
                size_t ob = ((size_t)bh*Ln + q0 + ql)*DKn + dk;
                *(float2*)&g_o[ob] =
                    make_float2(oacc[mt][ntd][0]+s0.x, oacc[mt][ntd][1]+s0.y);
                *(float2*)&g_o[ob + (size_t)8*DKn] =
                    make_float2(oacc[mt][ntd][2]+s8.x, oacc[mt][ntd][3]+s8.y);
            }
        }
    }
    #undef STAGE_K
    #undef STAGE_V
}

// ---------------------------------------------------------------------------
// Residual + LayerNorm (unchanged)
// ---------------------------------------------------------------------------
__global__ __launch_bounds__(256) void ln_kernel(const float* __restrict__ query,
                                                 const float* __restrict__ gamma,
                                                 const float* __restrict__ beta,
                                                 float* __restrict__ out) {
    const int row = blockIdx.x;
    const int b = row >> 11, l = row & (Ln-1);
    const int tid = threadIdx.x;
    float vals[4];
    float s = 0.f, ss = 0.f;
    #pragma unroll
    for (int it = 0; it < 4; it++) {
        int d = tid + it*256;
        int h = d >> 6, dk = d & 63;
        float o = g_o[(((size_t)(b*Hn + h))*Ln + l)*DKn + dk];
        float r = o + query[(size_t)row*Dn + d];
        vals[it] = r;
        s += r; ss += r*r;
    }
    __shared__ float sm[8], sq[8], stat[2];
    #pragma unroll
    for (int off = 16; off; off >>= 1) {
        s  += __shfl_xor_sync(0xffffffffu, s, off);
        ss += __shfl_xor_sync(0xffffffffu, ss, off);
    }
    int warp = tid >> 5, lane = tid & 31;
    if (lane == 0) { sm[warp] = s; sq[warp] = ss; }
    __syncthreads();
    if (tid == 0) {
        float S = 0.f, SS = 0.f;
        #pragma unroll
        for (int w = 0; w < 8; w++) { S += sm[w]; SS += sq[w]; }
        float mu = S * (1.0f/Dn);
        float var = SS * (1.0f/Dn) - mu*mu;
        stat[0] = mu;
        stat[1] = rsqrtf(var + 1e-6f);
    }
    __syncthreads();
    float mu = stat[0], rstd = stat[1];
    #pragma unroll
    for (int it = 0; it < 4; it++) {
        int d = tid + it*256;
        out[(size_t)row*Dn + d] = (vals[it] - mu) * rstd * gamma[d] + beta[d];
    }
}

// ---------------------------------------------------------------------------
extern "C" void kernel_launch(void* const* d_in, const int* in_sizes, int n_in,
                              void* d_out, int out_size) {
    const float* key   = (const float*)d_in[0];
    const float* value = (const float*)d_in[1];
    const float* query = (const float*)d_in[2];
    const int*   mask  = (const int*)d_in[3];
    const float* Wk = (const float*)d_in[4];
    const float* Wv = (const float*)d_in[5];
    const float* Wq = (const float*)d_in[6];
    const float* lng = (const float*)d_in[7];
    const float* lnb = (const float*)d_in[8];

    float* normed = (float*)d_out;                       // [B, L, D]
    float* attn;
    if ((size_t)out_size > (size_t)Bn*Ln*Dn) {
        attn = normed + (size_t)Bn*Ln*Dn;                // [B*H, L, L]
    } else {
        cudaGetSymbolAddress((void**)&attn, g_sc);
    }

    cudaFuncSetAttribute(proj_kernel,
                         cudaFuncAttributeMaxDynamicSharedMemorySize, PROJ_SMEM);
    cudaFuncSetAttribute(fused_kernel,
                         cudaFuncAttributeMaxDynamicSharedMemorySize, FUSED_SMEM);

    dim3 gp(4, Dn/128, Mn/128);   // x=0..2 proj K/V/Q, x=3 mask (interleaved)
    proj_kernel<<<gp, 256, PROJ_SMEM>>>(key, value, query, Wk, Wv, Wq, mask);

    dim3 gf(Ln/128, BHn);         // (16, 32)
    fused_kernel<<<gf, 256, FUSED_SMEM>>>(attn);

    ln_kernel<<<Mn, 256>>>(query, lng, lnb, normed);
}